// round 12
// baseline (speedup 1.0000x reference)
#include <cuda_runtime.h>
#include <cuda_bf16.h>
#include <math.h>
#include <stdint.h>

#define M_TOK   8192     // B*S
#define DD      256      // hidden dim
#define KDIM    512      // combined input dim
#define VDIM    512      // virtual output dim (tau/forcing interleaved)
#define NLAYERS 4
#define TMAX    50

#define MT 128           // M tile per CTA
#define NT 256           // N tile per CTA (TMEM D cols)
#define STAGE_BYTES 98304    // Ahi 16K + Alo 16K + Bhi 32K + Blo 32K
#define DYN_SMEM (2*STAGE_BYTES + 1024)   // +1024 for manual alignment

// idesc kind::f16: dtype=F32, atype=btype=BF16, N=256, M=128
#define IDESC 0x8400490u

// Arch gate: tcgen05 only in the sm_103a pass; baseline compute_103 pass
// gets the fp32 FFMA fallback.
#if defined(__CUDA_ARCH__) && (__CUDA_ARCH__ == 1030) && \
    (defined(__CUDA_ARCH_FEAT_SM103_ALL) || defined(__CUDA_ARCH_SPECIFIC__))
#define TC_PATH 1
#else
#define TC_PATH 0
#endif

// ---------------- device globals (allocation-free scratch) ----------------
// bf16 planes stored PRE-SWIZZLED, k-blocked: elem (kb, m, c) at
// (kb*8192 + m)*64 + (c ^ ((m&7)<<3)) — 16 KB contiguous per (kb, 128-row
// tile), byte-identical to the SW128 smem tile image.
__device__ __align__(256) float          g_s32[2][NLAYERS][M_TOK*DD];  // fp32 states
__device__ __align__(256) __nv_bfloat16  g_sbh[2][NLAYERS][M_TOK*DD];  // bf16 hi plane (swizzled)
__device__ __align__(256) __nv_bfloat16  g_sbl[2][NLAYERS][M_TOK*DD];  // bf16 lo plane (swizzled)
__device__ __align__(256) float          g_x32[M_TOK*DD];
__device__ __align__(256) __nv_bfloat16  g_xh[M_TOK*DD];               // swizzled
__device__ __align__(256) __nv_bfloat16  g_xl[M_TOK*DD];               // swizzled
// weights: [l][vt(2)][kb(8)] blocks of 256x64 swizzled = 16384 elems each
__device__ __align__(256) __nv_bfloat16  g_wh[NLAYERS*VDIM*KDIM];
__device__ __align__(256) __nv_bfloat16  g_wl[NLAYERS*VDIM*KDIM];
__device__ __align__(256) float          g_Wp[NLAYERS*KDIM*VDIM];      // fp32 [l][k][v] (fallback)
__device__ float    g_bp[NLAYERS*VDIM];
__device__ int      g_done;
__device__ int      g_result;
__device__ unsigned g_delta;
__device__ int      g_last;
__device__ unsigned g_count;

// ---------------- inline PTX helpers ----------------
__device__ __forceinline__ uint32_t smem_u32(const void* p) {
    uint32_t a;
    asm("{ .reg .u64 t; cvta.to.shared.u64 t, %1; cvt.u32.u64 %0, t; }" : "=r"(a) : "l"(p));
    return a;
}

__device__ __forceinline__ uint64_t make_desc(uint32_t addr) {
    const uint64_t base = (2ULL << 61) | (1ULL << 46) | (64ULL << 32) | (1ULL << 16); // SW128, LBO=1, SBO=64
    return base | (uint64_t)((addr >> 4) & 0x3FFF);
}

#define MBAR_INIT(a, c) asm volatile("mbarrier.init.shared.b64 [%0], %1;" :: "r"(a), "r"(c) : "memory")
#define MBAR_EXPECT_TX(a, b) asm volatile("mbarrier.arrive.expect_tx.shared.b64 _, [%0], %1;" :: "r"(a), "r"(b) : "memory")
#define MBAR_WAIT(a, par) do { \
    uint32_t _m = (a), _p = (par), _d; \
    asm volatile("{\n\t.reg .pred p;\n\tmbarrier.try_wait.parity.acquire.cta.shared::cta.b64 p, [%1], %2;\n\tselp.b32 %0, 1, 0, p;\n\t}" \
        : "=r"(_d) : "r"(_m), "r"(_p) : "memory"); \
    if (!_d) { \
        asm volatile("{\n\t.reg .pred P1;\n\tWL_%=:\n\tmbarrier.try_wait.parity.acquire.cta.shared::cta.b64 P1, [%0], %1, 0x989680;\n\t@P1 bra.uni WD_%=;\n\tbra.uni WL_%=;\n\tWD_%=:\n\t}" \
            :: "r"(_m), "r"(_p) : "memory"); \
    } } while (0)

#define CLUSTER_SYNC() do { \
    asm volatile("barrier.cluster.arrive.aligned;" ::: "memory"); \
    asm volatile("barrier.cluster.wait.aligned;" ::: "memory"); } while (0)

#if TC_PATH
// multicast bulk copy: data + complete_tx delivered to the same smem offset /
// mbarrier offset in every CTA whose bit is set in mask.
#define CP_BULK_MC(dst, src, bytes, mbar, mask) \
    asm volatile("cp.async.bulk.shared::cluster.global.mbarrier::complete_tx::bytes.multicast::cluster [%0], [%1], %2, [%3], %4;" \
        :: "r"(dst), "l"(src), "r"(bytes), "r"(mbar), "h"((uint16_t)(mask)) : "memory")

#define MBAR_ARRIVE_RANK(addr, rank) \
    asm volatile("{\n\t.reg .b32 ra;\n\tmapa.shared::cluster.u32 ra, %0, %1;\n\tmbarrier.arrive.shared::cluster.b64 _, [ra];\n\t}" \
        :: "r"(addr), "r"(rank) : "memory")

#define TM_ALLOC(sa, n)   asm volatile("tcgen05.alloc.cta_group::1.sync.aligned.shared::cta.b32 [%0], %1;" :: "r"(sa), "r"(n) : "memory")
#define TM_DEALLOC(t, n)  asm volatile("tcgen05.dealloc.cta_group::1.sync.aligned.b32 %0, %1;" :: "r"(t), "r"(n))
#define TM_RELINQ()       asm volatile("tcgen05.relinquish_alloc_permit.cta_group::1.sync.aligned;")
#define TM_COMMIT(mb)     asm volatile("tcgen05.commit.cta_group::1.mbarrier::arrive::one.shared::cluster.b64 [%0];" :: "r"(mb) : "memory")
#define TM_WAIT_LD()      asm volatile("tcgen05.wait::ld.sync.aligned;" ::: "memory")
#define TM_FENCE_AFTER()  asm volatile("tcgen05.fence::after_thread_sync;" ::: "memory")
#define TM_FENCE_BEFORE() asm volatile("tcgen05.fence::before_thread_sync;" ::: "memory")

__device__ __forceinline__ void mma_f16_ss(uint32_t d, uint64_t a, uint64_t b, uint32_t idesc, bool en) {
    uint32_t e = en ? 1u : 0u;
    asm volatile(
        "{\n\t.reg .pred p;\n\tsetp.ne.u32 p, %5, 0;\n\t"
        "tcgen05.mma.cta_group::1.kind::f16 [%0], %1, %2, %3, {%4, %4, %4, %4}, p;\n\t}"
        :: "r"(d), "l"(a), "l"(b), "r"(idesc), "r"(0u), "r"(e) : "memory");
}

#define TM_LD_X32(r, ta) \
    asm volatile("tcgen05.ld.sync.aligned.32x32b.x32.b32 " \
        "{%0,%1,%2,%3,%4,%5,%6,%7,%8,%9,%10,%11,%12,%13,%14,%15," \
        "%16,%17,%18,%19,%20,%21,%22,%23,%24,%25,%26,%27,%28,%29,%30,%31}, [%32];" \
        : "=r"((r)[0]),"=r"((r)[1]),"=r"((r)[2]),"=r"((r)[3]),"=r"((r)[4]),"=r"((r)[5]),"=r"((r)[6]),"=r"((r)[7]), \
          "=r"((r)[8]),"=r"((r)[9]),"=r"((r)[10]),"=r"((r)[11]),"=r"((r)[12]),"=r"((r)[13]),"=r"((r)[14]),"=r"((r)[15]), \
          "=r"((r)[16]),"=r"((r)[17]),"=r"((r)[18]),"=r"((r)[19]),"=r"((r)[20]),"=r"((r)[21]),"=r"((r)[22]),"=r"((r)[23]), \
          "=r"((r)[24]),"=r"((r)[25]),"=r"((r)[26]),"=r"((r)[27]),"=r"((r)[28]),"=r"((r)[29]),"=r"((r)[30]),"=r"((r)[31]) \
        : "r"(ta))
#endif // TC_PATH

// ---------------------------------------------------------------
__global__ void init_kernel() {
    size_t idx = (size_t)blockIdx.x * blockDim.x + threadIdx.x;
    float4 z = make_float4(0.f, 0.f, 0.f, 0.f);
    if (idx < (size_t)NLAYERS * M_TOK * DD / 4) ((float4*)&g_s32[0][0][0])[idx] = z;
    if (idx < (size_t)NLAYERS * M_TOK * DD / 8) {
        ((float4*)&g_sbh[0][0][0])[idx] = z;
        ((float4*)&g_sbl[0][0][0])[idx] = z;
    }
    if (idx == 0) { g_done = 0; g_result = TMAX; g_delta = 0u; g_last = 0; g_count = 0u; }
}

__global__ void xcvt_kernel(const float* __restrict__ x) {
    int idx = blockIdx.x * blockDim.x + threadIdx.x;
    if (idx < M_TOK * DD) {
        float v = x[idx];
        g_x32[idx] = v;
        int m = idx >> 8, d = idx & 255;
        int kb = d >> 6, c = d & 63;
        size_t o = ((size_t)kb * 8192 + m) * 64 + (c ^ ((m & 7) << 3));  // swizzled
        __nv_bfloat16 hi = __float2bfloat16(v);
        g_xh[o] = hi;
        g_xl[o] = __float2bfloat16(v - __bfloat162float(hi));
    }
}

__global__ void pack_kernel(const float* __restrict__ Ws, const float* __restrict__ bs,
                            const float* __restrict__ Wi, const float* __restrict__ bi,
                            const float* __restrict__ Wt, const float* __restrict__ bt) {
    int idx = blockIdx.x * blockDim.x + threadIdx.x;
    int total = NLAYERS * KDIM * VDIM;
    if (idx < total) {
        int l = idx / (KDIM * VDIM);
        int rem = idx % (KDIM * VDIM);
        int k = rem / VDIM;
        int v = rem % VDIM;
        int d = v >> 1, half = v & 1;
        float w;
        if (half == 0)      w = Wt[(l * DD + d) * KDIM + k];
        else if (k < DD)    w = Wi[(l * DD + d) * DD + k];
        else                w = Ws[(l * DD + d) * DD + (k - DD)];
        g_Wp[idx] = w;                                    // fp32 [l][k][v] (fallback)
        // bf16 swizzled blocks: [l][vt][kb] of 256x64
        int vt = v >> 8, vl = v & 255, kb = k >> 6, c = k & 63;
        size_t o = (size_t)(((l * 2 + vt) * 8 + kb)) * 16384 + vl * 64 + (c ^ ((vl & 7) << 3));
        __nv_bfloat16 hi = __float2bfloat16(w);
        g_wh[o] = hi;
        g_wl[o] = __float2bfloat16(w - __bfloat162float(hi));
    }
    if (idx < NLAYERS * VDIM) {
        int l = idx / VDIM, v = idx % VDIM, d = v >> 1, half = v & 1;
        g_bp[idx] = half ? (bs[l * DD + d] + bi[l * DD + d]) : bt[l * DD + d];
    }
}

// epilogue scalar: intrinsic transcendentals (inf-safe at saturation)
__device__ __forceinline__ float epi_update(float pt, float pf, float h, float& dmax) {
    float e   = __expf(-pt);                       // sigmoid; pt<<0 -> e=inf -> tau=0
    float tau = __fdividef(1.f, 1.f + e);
    float ax  = fabsf(pf);
    float e2  = __expf(ax + ax);                   // |pf| large -> inf -> th=1
    float th  = 1.f - __fdividef(2.f, e2 + 1.f);
    float forc = copysignf(th, pf);
    float hn = h + 0.05f * (forc - __fdividef(h, tau + 1e-6f));
    hn = fminf(10.f, fmaxf(-10.f, hn));
    dmax = fmaxf(dmax, fabsf(hn - h));
    return hn;
}

// fused convergence check (runs in last CTA of the l==3 kernel)
__device__ __forceinline__ void fused_check(int t) {
    __threadfence();
    unsigned c = atomicAdd(&g_count, 1u);
    if (c == 127u) {
        unsigned dbits = atomicMax(&g_delta, 0u);   // coherent read
        g_count = 0u;
        g_last = (t & 1) ^ 1;
        if (__uint_as_float(dbits) < 1e-3f) { g_done = 1; g_result = t; }
        g_delta = 0u;
    }
}

// One layer-step: GEMM [8192x512]x[512x512]^T + fused epilogue + delta reduce.
// Cluster (4,2): A-planes multicast across the vt pair, B quarters across 4 m-CTAs.
__global__ __launch_bounds__(256, 1) __cluster_dims__(4, 2, 1)
void layer_kernel(int l, int rb, int t) {
    if (g_done) return;

    extern __shared__ char dynsmem[];
    const int tid = threadIdx.x;

#if TC_PATH
    // ================= tcgen05 split-bf16, multicast + non-blocking dispatch =================
    __shared__ uint32_t s_tmem;
    __shared__ __align__(8) uint64_t s_mbar[6];   // full[2], mma[2], empty[2]
    __shared__ float s_red[8];

    const int wid = tid >> 5, lane = tid & 31;
    const int m0 = blockIdx.x * MT;
    const int vt = blockIdx.y;           // 0 or 1
    const int v0 = vt * NT;
    const int cx = blockIdx.x & 3;       // cluster coords (4,2)
    const int cy = blockIdx.y & 1;
    const uint16_t amask = (uint16_t)((1u << cx) | (1u << (cx + 4)));  // vt pair, same cx
    const uint16_t bmask = (uint16_t)(0xFu << (4 * cy));               // 4 m-CTAs, same vt

    const __nv_bfloat16* __restrict__ cin_h = (l == 0) ? g_xh : g_sbh[rb ^ 1][l - 1];
    const __nv_bfloat16* __restrict__ cin_l = (l == 0) ? g_xl : g_sbl[rb ^ 1][l - 1];
    const __nv_bfloat16* __restrict__ hp_h  = g_sbh[rb][l];
    const __nv_bfloat16* __restrict__ hp_l  = g_sbl[rb][l];
    const float* __restrict__ hp32          = g_s32[rb][l];
    float* __restrict__ o32                 = g_s32[rb ^ 1][l];
    __nv_bfloat16* __restrict__ obh         = g_sbh[rb ^ 1][l];
    __nv_bfloat16* __restrict__ obl         = g_sbl[rb ^ 1][l];
    const __nv_bfloat16* __restrict__ wbh   = g_wh + (size_t)((l * 2 + vt) * 8) * 16384;
    const __nv_bfloat16* __restrict__ wbl   = g_wl + (size_t)((l * 2 + vt) * 8) * 16384;

    uint32_t full_mb[2], mma_mb[2], empty_mb[2];
    full_mb[0]  = smem_u32(&s_mbar[0]); full_mb[1]  = smem_u32(&s_mbar[1]);
    mma_mb[0]   = smem_u32(&s_mbar[2]); mma_mb[1]   = smem_u32(&s_mbar[3]);
    empty_mb[0] = smem_u32(&s_mbar[4]); empty_mb[1] = smem_u32(&s_mbar[5]);
    if (tid == 0) {
        MBAR_INIT(full_mb[0], 1); MBAR_INIT(full_mb[1], 1);
        MBAR_INIT(mma_mb[0], 1);  MBAR_INIT(mma_mb[1], 1);
        MBAR_INIT(empty_mb[0], 8); MBAR_INIT(empty_mb[1], 8);   // one arrive per cluster CTA
    }
    if (wid == 0) TM_ALLOC(smem_u32(&s_tmem), NT);
    __syncthreads();
    uint32_t tmem;
    asm volatile("ld.shared.b32 %0, [%1];" : "=r"(tmem) : "r"(smem_u32(&s_tmem)));

    const uint32_t sbase = (smem_u32(dynsmem) + 1023u) & ~1023u;   // SW128 needs 1024-align

    // all peers' mbarriers must be init'd before any multicast targets them
    CLUSTER_SYNC();

    if (tid == 0) {
        // Per stage each CTA issues 2 multicast bulk ops:
        //   A-plane (hi if cy==0 else lo) of its own m-tile   -> vt pair  (16 KB)
        //   B quarter cx of [Bhi|Blo] for its own vt          -> 4 m-CTAs (16 KB)
        // Every CTA receives the full 96 KB stage (expect_tx from 6 ops).
        auto issue_loads = [&](int kb, uint32_t stage, uint32_t fmb) {
            MBAR_EXPECT_TX(fmb, (uint32_t)STAGE_BYTES);
            const __nv_bfloat16* ah; const __nv_bfloat16* al; int akb;
            if (kb < 4) { ah = cin_h; al = cin_l; akb = kb; }
            else        { ah = hp_h;  al = hp_l;  akb = kb - 4; }
            const __nv_bfloat16* asrc = (cy ? al : ah) + ((size_t)akb * 8192 + m0) * 64;
            CP_BULK_MC(stage + cy * 16384, asrc, 16384u, fmb, amask);
            const __nv_bfloat16* bsrc = ((cx < 2) ? (wbh + cx * 8192) : (wbl + (cx - 2) * 8192))
                                        + (size_t)kb * 16384;
            CP_BULK_MC(stage + 32768 + cx * 16384, bsrc, 16384u, fmb, bmask);
        };

        issue_loads(0, sbase, full_mb[0]);
        issue_loads(1, sbase + STAGE_BYTES, full_mb[1]);

        for (int kb = 0; kb < 8; kb++) {
            const int s = kb & 1, ph = (kb >> 1) & 1;
            const uint32_t stage = sbase + s * STAGE_BYTES;
            MBAR_WAIT(full_mb[s], ph);

            uint64_t dah = make_desc(stage);
            uint64_t dal = make_desc(stage + 16384);
            uint64_t dbh = make_desc(stage + 32768);
            uint64_t dbl = make_desc(stage + 65536);
#pragma unroll
            for (int pass = 0; pass < 3; pass++) {
                uint64_t da = (pass == 2) ? dal : dah;
                uint64_t db = (pass == 1) ? dbl : dbh;
#pragma unroll
                for (int kc = 0; kc < 4; kc++)
                    mma_f16_ss(tmem, da + kc * 2, db + kc * 2, IDESC,
                               !(kb == 0 && pass == 0 && kc == 0));
            }
            TM_COMMIT(mma_mb[s]);

            // Recycle the PREVIOUS stage while this stage's MMAs execute:
            // its MMAs completed before ours started (in-order tensor pipe),
            // so the waits below overlap with live MMA work.
            if (kb >= 1 && kb < 7) {
                const int sp = (kb - 1) & 1, php = ((kb - 1) >> 1) & 1;
                MBAR_WAIT(mma_mb[sp], php);        // prev-stage reads done (ours)
#pragma unroll
                for (int r = 0; r < 8; r++) MBAR_ARRIVE_RANK(empty_mb[sp], r);
                MBAR_WAIT(empty_mb[sp], php);      // all 8 CTAs done with stage sp
                issue_loads(kb + 1, sbase + sp * STAGE_BYTES, full_mb[sp]);
            }
        }
        MBAR_WAIT(mma_mb[1], 1);                   // final MMA (kb=7) done
    }
    __syncthreads();
    TM_FENCE_AFTER();

    // -------- fused epilogue: 8 warps; warp w -> rows (w&3)*32, col-half w>>2 --------
    float dmax = 0.f;
    {
        const int m = m0 + (wid & 3) * 32 + lane;
        const int cb0 = (wid >> 2) * 4;
        const float* hp = hp32 + (size_t)m * DD;
        float* orow = o32 + (size_t)m * DD;
        const int sw = (m & 7) << 3;
#pragma unroll
        for (int ci = 0; ci < 4; ci++) {
            const int cb = cb0 + ci;
            uint32_t r[32];
            TM_LD_X32(r, tmem + cb * 32);
            TM_WAIT_LD();
            const int dbase = (v0 >> 1) + cb * 16;
            const float* bp = &g_bp[l * VDIM + v0 + cb * 32];
            __align__(16) float hnv[16];
            __align__(16) __nv_bfloat16 hib[16], lob[16];
#pragma unroll
            for (int j = 0; j < 16; j++) {
                float pt = __uint_as_float(r[2 * j])     + bp[2 * j];
                float pf = __uint_as_float(r[2 * j + 1]) + bp[2 * j + 1];
                float hn = epi_update(pt, pf, hp[dbase + j], dmax);
                hnv[j] = hn;
                __nv_bfloat16 hi = __float2bfloat16(hn);
                hib[j] = hi;
                lob[j] = __float2bfloat16(hn - __bfloat162float(hi));
            }
#pragma unroll
            for (int q = 0; q < 4; q++)
                *(float4*)&orow[dbase + q * 4] = *(float4*)&hnv[q * 4];
            // swizzled k-blocked plane stores (2x16B per plane)
            const int kbd = dbase >> 6, c0 = dbase & 63;
            const size_t eb = ((size_t)kbd * 8192 + m) * 64;
            *(uint4*)&obh[eb + (c0 ^ sw)]       = *(uint4*)&hib[0];
            *(uint4*)&obh[eb + ((c0 + 8) ^ sw)] = *(uint4*)&hib[8];
            *(uint4*)&obl[eb + (c0 ^ sw)]       = *(uint4*)&lob[0];
            *(uint4*)&obl[eb + ((c0 + 8) ^ sw)] = *(uint4*)&lob[8];
        }
        TM_FENCE_BEFORE();
#pragma unroll
        for (int o = 16; o; o >>= 1) dmax = fmaxf(dmax, __shfl_xor_sync(0xffffffffu, dmax, o));
        if (lane == 0) s_red[wid] = dmax;
    }
    __syncthreads();
    if (tid == 0) {
        float v = s_red[0];
#pragma unroll
        for (int w = 1; w < 8; w++) v = fmaxf(v, s_red[w]);
        atomicMax(&g_delta, __float_as_uint(v));
        if (l == 3) fused_check(t);
    }
    __syncthreads();
    if (wid == 0) { TM_RELINQ(); TM_DEALLOC(tmem, NT); }

#else
    // ================= fp32 FFMA fallback (baseline compile pass) =================
    float* As = (float*)dynsmem;                  // [16][128]
    float* Bs = (float*)(dynsmem + 16 * 128 * 4); // [16][64]
    __shared__ float red[8];

    const float* __restrict__ curin = (l == 0) ? g_x32 : g_s32[rb ^ 1][l - 1];
    const float* __restrict__ hprev = g_s32[rb][l];
    float* __restrict__ hout        = g_s32[rb ^ 1][l];
    const float* __restrict__ Wp    = &g_Wp[l * KDIM * VDIM];

    int ty = tid >> 4, tx = tid & 15;
    int m0 = blockIdx.x * 128;
    float dmax_all = 0.f;

    for (int vc = 0; vc < 4; vc++) {
        int v0 = blockIdx.y * NT + vc * 64;
        float acc[8][4];
#pragma unroll
        for (int i = 0; i < 8; i++)
#pragma unroll
            for (int j = 0; j < 4; j++) acc[i][j] = 0.f;

        for (int k0 = 0; k0 < KDIM; k0 += 16) {
            const float* Asrc = (k0 < DD) ? curin : hprev;
            int kb2 = k0 & (DD - 1);
            __syncthreads();
#pragma unroll
            for (int s = 0; s < 2; s++) {
                int slot = tid * 2 + s;
                int ml = slot >> 2, k4 = slot & 3;
                float4 va = *(const float4*)&Asrc[(size_t)(m0 + ml) * DD + kb2 + k4 * 4];
                As[(k4 * 4 + 0) * 128 + ml] = va.x; As[(k4 * 4 + 1) * 128 + ml] = va.y;
                As[(k4 * 4 + 2) * 128 + ml] = va.z; As[(k4 * 4 + 3) * 128 + ml] = va.w;
            }
            {
                int kk = tid >> 4, v4 = tid & 15;
                *(float4*)&Bs[kk * 64 + v4 * 4] =
                    *(const float4*)&Wp[(size_t)(k0 + kk) * VDIM + v0 + v4 * 4];
            }
            __syncthreads();
#pragma unroll
            for (int kk = 0; kk < 16; kk++) {
                float4 a0 = *(const float4*)&As[kk * 128 + ty * 8];
                float4 a1 = *(const float4*)&As[kk * 128 + ty * 8 + 4];
                float4 bb = *(const float4*)&Bs[kk * 64 + tx * 4];
                float a[8] = {a0.x, a0.y, a0.z, a0.w, a1.x, a1.y, a1.z, a1.w};
                float b[4] = {bb.x, bb.y, bb.z, bb.w};
#pragma unroll
                for (int i = 0; i < 8; i++)
#pragma unroll
                    for (int j = 0; j < 4; j++) acc[i][j] += a[i] * b[j];
            }
        }

        float bT0 = g_bp[l * VDIM + v0 + tx * 4 + 0];
        float bF0 = g_bp[l * VDIM + v0 + tx * 4 + 1];
        float bT1 = g_bp[l * VDIM + v0 + tx * 4 + 2];
        float bF1 = g_bp[l * VDIM + v0 + tx * 4 + 3];
        int d0 = (v0 >> 1) + tx * 2;
#pragma unroll
        for (int i = 0; i < 8; i++) {
            int m = m0 + ty * 8 + i;
#pragma unroll
            for (int q = 0; q < 2; q++) {
                float hn = epi_update(acc[i][2 * q] + (q ? bT1 : bT0),
                                      acc[i][2 * q + 1] + (q ? bF1 : bF0),
                                      hprev[(size_t)m * DD + d0 + q], dmax_all);
                hout[(size_t)m * DD + d0 + q] = hn;
            }
        }
    }
#pragma unroll
    for (int o = 16; o; o >>= 1) dmax_all = fmaxf(dmax_all, __shfl_xor_sync(0xffffffffu, dmax_all, o));
    if ((tid & 31) == 0) red[tid >> 5] = dmax_all;
    __syncthreads();
    if (tid == 0) {
        float v = red[0];
#pragma unroll
        for (int w = 1; w < 8; w++) v = fmaxf(v, red[w]);
        atomicMax(&g_delta, __float_as_uint(v));
        if (l == 3) fused_check(t);
    }
#endif
}

__global__ void output_kernel(float* __restrict__ out, int n) {
    int idx = blockIdx.x * blockDim.x + threadIdx.x;
    if (idx >= n) return;
    if (idx < M_TOK * DD) out[idx] = g_s32[g_last][NLAYERS - 1][idx];
    else                  out[idx] = (float)g_result;
}

// ---------------------------------------------------------------
extern "C" void kernel_launch(void* const* d_in, const int* in_sizes, int n_in,
                              void* d_out, int out_size) {
    const float* x  = (const float*)d_in[0];
    const float* Ws = (const float*)d_in[1];
    const float* bs = (const float*)d_in[2];
    const float* Wi = (const float*)d_in[3];
    const float* bi = (const float*)d_in[4];
    const float* Wt = (const float*)d_in[5];
    const float* bt = (const float*)d_in[6];

    static int attr_set = 0;
    if (!attr_set) {
        cudaFuncSetAttribute(layer_kernel, cudaFuncAttributeMaxDynamicSharedMemorySize, DYN_SMEM);
        attr_set = 1;
    }

    init_kernel<<<8192, 256>>>();
    xcvt_kernel<<<(M_TOK * DD + 255) / 256, 256>>>(x);
    pack_kernel<<<(NLAYERS * KDIM * VDIM + 255) / 256, 256>>>(Ws, bs, Wi, bi, Wt, bt);

    dim3 grid(M_TOK / MT, VDIM / NT);   // 64 x 2 = 128 CTAs, clusters of (4,2)
    for (int t = 0; t < TMAX; t++) {
        for (int l = 0; l < NLAYERS; l++)
            layer_kernel<<<grid, 256, DYN_SMEM>>>(l, t & 1, t);
    }
    output_kernel<<<(out_size + 255) / 256, 256>>>((float*)d_out, out_size);
}

// round 16
// speedup vs baseline: 1.7559x; 1.7559x over previous
#include <cuda_runtime.h>
#include <cuda_bf16.h>
#include <math.h>
#include <stdint.h>

#define M_TOK   8192     // B*S
#define DD      256      // hidden dim
#define KDIM    512      // combined input dim
#define VDIM    512      // virtual output dim (tau/forcing interleaved)
#define NLAYERS 4
#define TMAX    50

#define MT 128           // M tile per CTA
#define NT 256           // N tile per CTA (TMEM D cols)
#define STAGE_BYTES 98304    // Ahi 16K + Alo 16K + Bhi 32K + Blo 32K
#define DYN_SMEM (2*STAGE_BYTES + 1024)   // +1024 for manual alignment

// idesc kind::f16: dtype=F32, atype=btype=BF16, N=256, M=128
#define IDESC 0x8400490u

// Arch gate: tcgen05 only in the sm_103a pass; baseline compute_103 pass
// gets the fp32 FFMA fallback.
#if defined(__CUDA_ARCH__) && (__CUDA_ARCH__ == 1030) && \
    (defined(__CUDA_ARCH_FEAT_SM103_ALL) || defined(__CUDA_ARCH_SPECIFIC__))
#define TC_PATH 1
#else
#define TC_PATH 0
#endif

// ---------------- device globals (allocation-free scratch) ----------------
// bf16 planes stored PRE-SWIZZLED, k-blocked: elem (kb, m, c) at
// (kb*8192 + m)*64 + (c ^ ((m&7)<<3)) — 16 KB contiguous per (kb, 128-row
// tile), byte-identical to the SW128 smem tile image.
__device__ __align__(256) float          g_s32[2][NLAYERS][M_TOK*DD];  // fp32 states
__device__ __align__(256) __nv_bfloat16  g_sbh[2][NLAYERS][M_TOK*DD];  // bf16 hi plane (swizzled)
__device__ __align__(256) __nv_bfloat16  g_sbl[2][NLAYERS][M_TOK*DD];  // bf16 lo plane (swizzled)
__device__ __align__(256) float          g_x32[M_TOK*DD];
__device__ __align__(256) __nv_bfloat16  g_xh[M_TOK*DD];               // swizzled
__device__ __align__(256) __nv_bfloat16  g_xl[M_TOK*DD];               // swizzled
// weights: [l][vt(2)][kb(8)] blocks of 256x64 swizzled = 16384 elems each
__device__ __align__(256) __nv_bfloat16  g_wh[NLAYERS*VDIM*KDIM];
__device__ __align__(256) __nv_bfloat16  g_wl[NLAYERS*VDIM*KDIM];
__device__ __align__(256) float          g_Wp[NLAYERS*KDIM*VDIM];      // fp32 [l][k][v] (fallback)
__device__ float    g_bp[NLAYERS*VDIM];
__device__ int      g_done;
__device__ int      g_result;
__device__ unsigned g_delta;
__device__ int      g_last;
__device__ unsigned g_count;

// ---------------- inline PTX helpers ----------------
__device__ __forceinline__ uint32_t smem_u32(const void* p) {
    uint32_t a;
    asm("{ .reg .u64 t; cvta.to.shared.u64 t, %1; cvt.u32.u64 %0, t; }" : "=r"(a) : "l"(p));
    return a;
}

__device__ __forceinline__ uint64_t make_desc(uint32_t addr) {
    const uint64_t base = (2ULL << 61) | (1ULL << 46) | (64ULL << 32) | (1ULL << 16); // SW128, LBO=1, SBO=64
    return base | (uint64_t)((addr >> 4) & 0x3FFF);
}

#define MBAR_INIT(a, c) asm volatile("mbarrier.init.shared.b64 [%0], %1;" :: "r"(a), "r"(c) : "memory")
#define MBAR_EXPECT_TX(a, b) asm volatile("mbarrier.arrive.expect_tx.shared.b64 _, [%0], %1;" :: "r"(a), "r"(b) : "memory")
#define MBAR_WAIT(a, par) do { \
    uint32_t _m = (a), _p = (par), _d; \
    asm volatile("{\n\t.reg .pred p;\n\tmbarrier.try_wait.parity.acquire.cta.shared::cta.b64 p, [%1], %2;\n\tselp.b32 %0, 1, 0, p;\n\t}" \
        : "=r"(_d) : "r"(_m), "r"(_p) : "memory"); \
    if (!_d) { \
        asm volatile("{\n\t.reg .pred P1;\n\tWL_%=:\n\tmbarrier.try_wait.parity.acquire.cta.shared::cta.b64 P1, [%0], %1, 0x989680;\n\t@P1 bra.uni WD_%=;\n\tbra.uni WL_%=;\n\tWD_%=:\n\t}" \
            :: "r"(_m), "r"(_p) : "memory"); \
    } } while (0)

#define CLUSTER_SYNC() do { \
    asm volatile("barrier.cluster.arrive.aligned;" ::: "memory"); \
    asm volatile("barrier.cluster.wait.aligned;" ::: "memory"); } while (0)

#if TC_PATH
// multicast bulk copy: data + complete_tx delivered to the same smem offset /
// mbarrier offset in every CTA whose bit is set in mask.
#define CP_BULK_MC(dst, src, bytes, mbar, mask) \
    asm volatile("cp.async.bulk.shared::cluster.global.mbarrier::complete_tx::bytes.multicast::cluster [%0], [%1], %2, [%3], %4;" \
        :: "r"(dst), "l"(src), "r"(bytes), "r"(mbar), "h"((uint16_t)(mask)) : "memory")

#define MBAR_ARRIVE_RANK(addr, rank) \
    asm volatile("{\n\t.reg .b32 ra;\n\tmapa.shared::cluster.u32 ra, %0, %1;\n\tmbarrier.arrive.shared::cluster.b64 _, [ra];\n\t}" \
        :: "r"(addr), "r"(rank) : "memory")

#define TM_ALLOC(sa, n)   asm volatile("tcgen05.alloc.cta_group::1.sync.aligned.shared::cta.b32 [%0], %1;" :: "r"(sa), "r"(n) : "memory")
#define TM_DEALLOC(t, n)  asm volatile("tcgen05.dealloc.cta_group::1.sync.aligned.b32 %0, %1;" :: "r"(t), "r"(n))
#define TM_RELINQ()       asm volatile("tcgen05.relinquish_alloc_permit.cta_group::1.sync.aligned;")
#define TM_COMMIT(mb)     asm volatile("tcgen05.commit.cta_group::1.mbarrier::arrive::one.shared::cluster.b64 [%0];" :: "r"(mb) : "memory")
#define TM_WAIT_LD()      asm volatile("tcgen05.wait::ld.sync.aligned;" ::: "memory")
#define TM_FENCE_AFTER()  asm volatile("tcgen05.fence::after_thread_sync;" ::: "memory")
#define TM_FENCE_BEFORE() asm volatile("tcgen05.fence::before_thread_sync;" ::: "memory")

__device__ __forceinline__ void mma_f16_ss(uint32_t d, uint64_t a, uint64_t b, uint32_t idesc, bool en) {
    uint32_t e = en ? 1u : 0u;
    asm volatile(
        "{\n\t.reg .pred p;\n\tsetp.ne.u32 p, %5, 0;\n\t"
        "tcgen05.mma.cta_group::1.kind::f16 [%0], %1, %2, %3, {%4, %4, %4, %4}, p;\n\t}"
        :: "r"(d), "l"(a), "l"(b), "r"(idesc), "r"(0u), "r"(e) : "memory");
}

#define TM_LD_X32(r, ta) \
    asm volatile("tcgen05.ld.sync.aligned.32x32b.x32.b32 " \
        "{%0,%1,%2,%3,%4,%5,%6,%7,%8,%9,%10,%11,%12,%13,%14,%15," \
        "%16,%17,%18,%19,%20,%21,%22,%23,%24,%25,%26,%27,%28,%29,%30,%31}, [%32];" \
        : "=r"((r)[0]),"=r"((r)[1]),"=r"((r)[2]),"=r"((r)[3]),"=r"((r)[4]),"=r"((r)[5]),"=r"((r)[6]),"=r"((r)[7]), \
          "=r"((r)[8]),"=r"((r)[9]),"=r"((r)[10]),"=r"((r)[11]),"=r"((r)[12]),"=r"((r)[13]),"=r"((r)[14]),"=r"((r)[15]), \
          "=r"((r)[16]),"=r"((r)[17]),"=r"((r)[18]),"=r"((r)[19]),"=r"((r)[20]),"=r"((r)[21]),"=r"((r)[22]),"=r"((r)[23]), \
          "=r"((r)[24]),"=r"((r)[25]),"=r"((r)[26]),"=r"((r)[27]),"=r"((r)[28]),"=r"((r)[29]),"=r"((r)[30]),"=r"((r)[31]) \
        : "r"(ta))
#endif // TC_PATH

// ---------------------------------------------------------------
__global__ void init_kernel() {
    size_t idx = (size_t)blockIdx.x * blockDim.x + threadIdx.x;
    float4 z = make_float4(0.f, 0.f, 0.f, 0.f);
    if (idx < (size_t)NLAYERS * M_TOK * DD / 4) ((float4*)&g_s32[0][0][0])[idx] = z;
    if (idx < (size_t)NLAYERS * M_TOK * DD / 8) {
        ((float4*)&g_sbh[0][0][0])[idx] = z;
        ((float4*)&g_sbl[0][0][0])[idx] = z;
    }
    if (idx == 0) { g_done = 0; g_result = TMAX; g_delta = 0u; g_last = 0; g_count = 0u; }
}

__global__ void xcvt_kernel(const float* __restrict__ x) {
    int idx = blockIdx.x * blockDim.x + threadIdx.x;
    if (idx < M_TOK * DD) {
        float v = x[idx];
        g_x32[idx] = v;
        int m = idx >> 8, d = idx & 255;
        int kb = d >> 6, c = d & 63;
        size_t o = ((size_t)kb * 8192 + m) * 64 + (c ^ ((m & 7) << 3));  // swizzled
        __nv_bfloat16 hi = __float2bfloat16(v);
        g_xh[o] = hi;
        g_xl[o] = __float2bfloat16(v - __bfloat162float(hi));
    }
}

__global__ void pack_kernel(const float* __restrict__ Ws, const float* __restrict__ bs,
                            const float* __restrict__ Wi, const float* __restrict__ bi,
                            const float* __restrict__ Wt, const float* __restrict__ bt) {
    int idx = blockIdx.x * blockDim.x + threadIdx.x;
    int total = NLAYERS * KDIM * VDIM;
    if (idx < total) {
        int l = idx / (KDIM * VDIM);
        int rem = idx % (KDIM * VDIM);
        int k = rem / VDIM;
        int v = rem % VDIM;
        int d = v >> 1, half = v & 1;
        float w;
        if (half == 0)      w = Wt[(l * DD + d) * KDIM + k];
        else if (k < DD)    w = Wi[(l * DD + d) * DD + k];
        else                w = Ws[(l * DD + d) * DD + (k - DD)];
        g_Wp[idx] = w;                                    // fp32 [l][k][v] (fallback)
        // bf16 swizzled blocks: [l][vt][kb] of 256x64
        int vt = v >> 8, vl = v & 255, kb = k >> 6, c = k & 63;
        size_t o = (size_t)(((l * 2 + vt) * 8 + kb)) * 16384 + vl * 64 + (c ^ ((vl & 7) << 3));
        __nv_bfloat16 hi = __float2bfloat16(w);
        g_wh[o] = hi;
        g_wl[o] = __float2bfloat16(w - __bfloat162float(hi));
    }
    if (idx < NLAYERS * VDIM) {
        int l = idx / VDIM, v = idx % VDIM, d = v >> 1, half = v & 1;
        g_bp[idx] = half ? (bs[l * DD + d] + bi[l * DD + d]) : bt[l * DD + d];
    }
}

// epilogue scalar: intrinsic transcendentals (inf-safe at saturation)
__device__ __forceinline__ float epi_update(float pt, float pf, float h, float& dmax) {
    float e   = __expf(-pt);                       // sigmoid; pt<<0 -> e=inf -> tau=0
    float tau = __fdividef(1.f, 1.f + e);
    float ax  = fabsf(pf);
    float e2  = __expf(ax + ax);                   // |pf| large -> inf -> th=1
    float th  = 1.f - __fdividef(2.f, e2 + 1.f);
    float forc = copysignf(th, pf);
    float hn = h + 0.05f * (forc - __fdividef(h, tau + 1e-6f));
    hn = fminf(10.f, fmaxf(-10.f, hn));
    dmax = fmaxf(dmax, fabsf(hn - h));
    return hn;
}

// fused convergence check (runs in last CTA of the l==3 kernel)
__device__ __forceinline__ void fused_check(int t) {
    __threadfence();
    unsigned c = atomicAdd(&g_count, 1u);
    if (c == 127u) {
        unsigned dbits = atomicMax(&g_delta, 0u);   // coherent read
        g_count = 0u;
        g_last = (t & 1) ^ 1;
        if (__uint_as_float(dbits) < 1e-3f) { g_done = 1; g_result = t; }
        g_delta = 0u;
    }
}

// One layer-step: GEMM [8192x512]x[512x512]^T + fused epilogue + delta reduce.
// Cluster (2,2): A-planes multicast across the vt pair, B-planes across the m pair.
// Non-blocking dispatch: stage s-1 is recycled WHILE stage s MMAs execute.
__global__ __launch_bounds__(256, 1) __cluster_dims__(2, 2, 1)
void layer_kernel(int l, int rb, int t) {
    if (g_done) return;

    extern __shared__ char dynsmem[];
    const int tid = threadIdx.x;

#if TC_PATH
    // ================= tcgen05 split-bf16, multicast + non-blocking dispatch =================
    __shared__ uint32_t s_tmem;
    __shared__ __align__(8) uint64_t s_mbar[6];   // full[2], mma[2], empty[2]
    __shared__ float s_red[8];

    const int wid = tid >> 5, lane = tid & 31;
    const int m0 = blockIdx.x * MT;
    const int vt = blockIdx.y;           // 0 or 1
    const int v0 = vt * NT;
    const int cx = blockIdx.x & 1;       // cluster coords (2,2)
    const int cy = blockIdx.y & 1;
    const uint16_t amask = (uint16_t)((1u << cx) | (1u << (cx + 2)));  // same-x pair
    const uint16_t bmask = (uint16_t)(3u << (2 * cy));                 // same-y pair

    const __nv_bfloat16* __restrict__ cin_h = (l == 0) ? g_xh : g_sbh[rb ^ 1][l - 1];
    const __nv_bfloat16* __restrict__ cin_l = (l == 0) ? g_xl : g_sbl[rb ^ 1][l - 1];
    const __nv_bfloat16* __restrict__ hp_h  = g_sbh[rb][l];
    const __nv_bfloat16* __restrict__ hp_l  = g_sbl[rb][l];
    const float* __restrict__ hp32          = g_s32[rb][l];
    float* __restrict__ o32                 = g_s32[rb ^ 1][l];
    __nv_bfloat16* __restrict__ obh         = g_sbh[rb ^ 1][l];
    __nv_bfloat16* __restrict__ obl         = g_sbl[rb ^ 1][l];
    const __nv_bfloat16* __restrict__ wbh   = g_wh + (size_t)((l * 2 + vt) * 8) * 16384;
    const __nv_bfloat16* __restrict__ wbl   = g_wl + (size_t)((l * 2 + vt) * 8) * 16384;

    uint32_t full_mb[2], mma_mb[2], empty_mb[2];
    full_mb[0]  = smem_u32(&s_mbar[0]); full_mb[1]  = smem_u32(&s_mbar[1]);
    mma_mb[0]   = smem_u32(&s_mbar[2]); mma_mb[1]   = smem_u32(&s_mbar[3]);
    empty_mb[0] = smem_u32(&s_mbar[4]); empty_mb[1] = smem_u32(&s_mbar[5]);
    if (tid == 0) {
        MBAR_INIT(full_mb[0], 1); MBAR_INIT(full_mb[1], 1);
        MBAR_INIT(mma_mb[0], 1);  MBAR_INIT(mma_mb[1], 1);
        MBAR_INIT(empty_mb[0], 4); MBAR_INIT(empty_mb[1], 4);   // one arrive per cluster CTA
    }
    if (wid == 0) TM_ALLOC(smem_u32(&s_tmem), NT);
    __syncthreads();
    uint32_t tmem;
    asm volatile("ld.shared.b32 %0, [%1];" : "=r"(tmem) : "r"(smem_u32(&s_tmem)));

    const uint32_t sbase = (smem_u32(dynsmem) + 1023u) & ~1023u;   // SW128 needs 1024-align

    // all peers' mbarriers must be init'd before any multicast targets them
    CLUSTER_SYNC();

    if (tid == 0) {
        // Each CTA issues 2 multicast bulk ops per stage:
        //   A-plane (hi if cy==0 else lo) of its own m-tile  -> vt pair
        //   B-plane (hi if cx==0 else lo) of its own vt      -> m pair
        // and receives the full 96 KB stage (expect_tx local, tx from 4 ops).
        auto issue_loads = [&](int kb, uint32_t stage, uint32_t fmb) {
            MBAR_EXPECT_TX(fmb, (uint32_t)STAGE_BYTES);
            const __nv_bfloat16* ah; const __nv_bfloat16* al; int akb;
            if (kb < 4) { ah = cin_h; al = cin_l; akb = kb; }
            else        { ah = hp_h;  al = hp_l;  akb = kb - 4; }
            const __nv_bfloat16* asrc = (cy ? al : ah) + ((size_t)akb * 8192 + m0) * 64;
            CP_BULK_MC(stage + cy * 16384, asrc, 16384u, fmb, amask);
            const __nv_bfloat16* bsrc = (cx ? wbl : wbh) + (size_t)kb * 16384;
            CP_BULK_MC(stage + 32768 + cx * 32768, bsrc, 32768u, fmb, bmask);
        };

        issue_loads(0, sbase, full_mb[0]);
        issue_loads(1, sbase + STAGE_BYTES, full_mb[1]);

        for (int kb = 0; kb < 8; kb++) {
            const int s = kb & 1, ph = (kb >> 1) & 1;
            const uint32_t stage = sbase + s * STAGE_BYTES;
            MBAR_WAIT(full_mb[s], ph);

            uint64_t dah = make_desc(stage);
            uint64_t dal = make_desc(stage + 16384);
            uint64_t dbh = make_desc(stage + 32768);
            uint64_t dbl = make_desc(stage + 65536);
#pragma unroll
            for (int pass = 0; pass < 3; pass++) {
                uint64_t da = (pass == 2) ? dal : dah;
                uint64_t db = (pass == 1) ? dbl : dbh;
#pragma unroll
                for (int kc = 0; kc < 4; kc++)
                    mma_f16_ss(tmem, da + kc * 2, db + kc * 2, IDESC,
                               !(kb == 0 && pass == 0 && kc == 0));
            }
            TM_COMMIT(mma_mb[s]);

            // Recycle the PREVIOUS stage while this stage's MMAs execute:
            // its MMAs completed before ours started (in-order tensor pipe),
            // so these waits overlap with live MMA work instead of draining it.
            if (kb >= 1 && kb < 7) {
                const int sp = (kb - 1) & 1, php = ((kb - 1) >> 1) & 1;
                MBAR_WAIT(mma_mb[sp], php);        // prev-stage reads done (ours)
#pragma unroll
                for (int r = 0; r < 4; r++) MBAR_ARRIVE_RANK(empty_mb[sp], r);
                MBAR_WAIT(empty_mb[sp], php);      // all 4 CTAs done with stage sp
                issue_loads(kb + 1, sbase + sp * STAGE_BYTES, full_mb[sp]);
            }
        }
        MBAR_WAIT(mma_mb[1], 1);                   // final MMA (kb=7) done
    }
    __syncthreads();
    TM_FENCE_AFTER();

    // -------- fused epilogue: 8 warps; warp w -> rows (w&3)*32, col-half w>>2 --------
    float dmax = 0.f;
    {
        const int m = m0 + (wid & 3) * 32 + lane;
        const int cb0 = (wid >> 2) * 4;
        const float* hp = hp32 + (size_t)m * DD;
        float* orow = o32 + (size_t)m * DD;
        const int sw = (m & 7) << 3;
#pragma unroll
        for (int ci = 0; ci < 4; ci++) {
            const int cb = cb0 + ci;
            uint32_t r[32];
            TM_LD_X32(r, tmem + cb * 32);
            TM_WAIT_LD();
            const int dbase = (v0 >> 1) + cb * 16;
            const float* bp = &g_bp[l * VDIM + v0 + cb * 32];
            __align__(16) float hnv[16];
            __align__(16) __nv_bfloat16 hib[16], lob[16];
#pragma unroll
            for (int j = 0; j < 16; j++) {
                float pt = __uint_as_float(r[2 * j])     + bp[2 * j];
                float pf = __uint_as_float(r[2 * j + 1]) + bp[2 * j + 1];
                float hn = epi_update(pt, pf, hp[dbase + j], dmax);
                hnv[j] = hn;
                __nv_bfloat16 hi = __float2bfloat16(hn);
                hib[j] = hi;
                lob[j] = __float2bfloat16(hn - __bfloat162float(hi));
            }
#pragma unroll
            for (int q = 0; q < 4; q++)
                *(float4*)&orow[dbase + q * 4] = *(float4*)&hnv[q * 4];
            // swizzled k-blocked plane stores (2x16B per plane)
            const int kbd = dbase >> 6, c0 = dbase & 63;
            const size_t eb = ((size_t)kbd * 8192 + m) * 64;
            *(uint4*)&obh[eb + (c0 ^ sw)]       = *(uint4*)&hib[0];
            *(uint4*)&obh[eb + ((c0 + 8) ^ sw)] = *(uint4*)&hib[8];
            *(uint4*)&obl[eb + (c0 ^ sw)]       = *(uint4*)&lob[0];
            *(uint4*)&obl[eb + ((c0 + 8) ^ sw)] = *(uint4*)&lob[8];
        }
        TM_FENCE_BEFORE();
#pragma unroll
        for (int o = 16; o; o >>= 1) dmax = fmaxf(dmax, __shfl_xor_sync(0xffffffffu, dmax, o));
        if (lane == 0) s_red[wid] = dmax;
    }
    __syncthreads();
    if (tid == 0) {
        float v = s_red[0];
#pragma unroll
        for (int w = 1; w < 8; w++) v = fmaxf(v, s_red[w]);
        atomicMax(&g_delta, __float_as_uint(v));
        if (l == 3) fused_check(t);
    }
    __syncthreads();
    if (wid == 0) { TM_RELINQ(); TM_DEALLOC(tmem, NT); }

#else
    // ================= fp32 FFMA fallback (baseline compile pass) =================
    float* As = (float*)dynsmem;                  // [16][128]
    float* Bs = (float*)(dynsmem + 16 * 128 * 4); // [16][64]
    __shared__ float red[8];

    const float* __restrict__ curin = (l == 0) ? g_x32 : g_s32[rb ^ 1][l - 1];
    const float* __restrict__ hprev = g_s32[rb][l];
    float* __restrict__ hout        = g_s32[rb ^ 1][l];
    const float* __restrict__ Wp    = &g_Wp[l * KDIM * VDIM];

    int ty = tid >> 4, tx = tid & 15;
    int m0 = blockIdx.x * 128;
    float dmax_all = 0.f;

    for (int vc = 0; vc < 4; vc++) {
        int v0 = blockIdx.y * NT + vc * 64;
        float acc[8][4];
#pragma unroll
        for (int i = 0; i < 8; i++)
#pragma unroll
            for (int j = 0; j < 4; j++) acc[i][j] = 0.f;

        for (int k0 = 0; k0 < KDIM; k0 += 16) {
            const float* Asrc = (k0 < DD) ? curin : hprev;
            int kb2 = k0 & (DD - 1);
            __syncthreads();
#pragma unroll
            for (int s = 0; s < 2; s++) {
                int slot = tid * 2 + s;
                int ml = slot >> 2, k4 = slot & 3;
                float4 va = *(const float4*)&Asrc[(size_t)(m0 + ml) * DD + kb2 + k4 * 4];
                As[(k4 * 4 + 0) * 128 + ml] = va.x; As[(k4 * 4 + 1) * 128 + ml] = va.y;
                As[(k4 * 4 + 2) * 128 + ml] = va.z; As[(k4 * 4 + 3) * 128 + ml] = va.w;
            }
            {
                int kk = tid >> 4, v4 = tid & 15;
                *(float4*)&Bs[kk * 64 + v4 * 4] =
                    *(const float4*)&Wp[(size_t)(k0 + kk) * VDIM + v0 + v4 * 4];
            }
            __syncthreads();
#pragma unroll
            for (int kk = 0; kk < 16; kk++) {
                float4 a0 = *(const float4*)&As[kk * 128 + ty * 8];
                float4 a1 = *(const float4*)&As[kk * 128 + ty * 8 + 4];
                float4 bb = *(const float4*)&Bs[kk * 64 + tx * 4];
                float a[8] = {a0.x, a0.y, a0.z, a0.w, a1.x, a1.y, a1.z, a1.w};
                float b[4] = {bb.x, bb.y, bb.z, bb.w};
#pragma unroll
                for (int i = 0; i < 8; i++)
#pragma unroll
                    for (int j = 0; j < 4; j++) acc[i][j] += a[i] * b[j];
            }
        }

        float bT0 = g_bp[l * VDIM + v0 + tx * 4 + 0];
        float bF0 = g_bp[l * VDIM + v0 + tx * 4 + 1];
        float bT1 = g_bp[l * VDIM + v0 + tx * 4 + 2];
        float bF1 = g_bp[l * VDIM + v0 + tx * 4 + 3];
        int d0 = (v0 >> 1) + tx * 2;
#pragma unroll
        for (int i = 0; i < 8; i++) {
            int m = m0 + ty * 8 + i;
#pragma unroll
            for (int q = 0; q < 2; q++) {
                float hn = epi_update(acc[i][2 * q] + (q ? bT1 : bT0),
                                      acc[i][2 * q + 1] + (q ? bF1 : bF0),
                                      hprev[(size_t)m * DD + d0 + q], dmax_all);
                hout[(size_t)m * DD + d0 + q] = hn;
            }
        }
    }
#pragma unroll
    for (int o = 16; o; o >>= 1) dmax_all = fmaxf(dmax_all, __shfl_xor_sync(0xffffffffu, dmax_all, o));
    if ((tid & 31) == 0) red[tid >> 5] = dmax_all;
    __syncthreads();
    if (tid == 0) {
        float v = red[0];
#pragma unroll
        for (int w = 1; w < 8; w++) v = fmaxf(v, red[w]);
        atomicMax(&g_delta, __float_as_uint(v));
        if (l == 3) fused_check(t);
    }
#endif
}

__global__ void output_kernel(float* __restrict__ out, int n) {
    int idx = blockIdx.x * blockDim.x + threadIdx.x;
    if (idx >= n) return;
    if (idx < M_TOK * DD) out[idx] = g_s32[g_last][NLAYERS - 1][idx];
    else                  out[idx] = (float)g_result;
}

// ---------------------------------------------------------------
extern "C" void kernel_launch(void* const* d_in, const int* in_sizes, int n_in,
                              void* d_out, int out_size) {
    const float* x  = (const float*)d_in[0];
    const float* Ws = (const float*)d_in[1];
    const float* bs = (const float*)d_in[2];
    const float* Wi = (const float*)d_in[3];
    const float* bi = (const float*)d_in[4];
    const float* Wt = (const float*)d_in[5];
    const float* bt = (const float*)d_in[6];

    static int attr_set = 0;
    if (!attr_set) {
        cudaFuncSetAttribute(layer_kernel, cudaFuncAttributeMaxDynamicSharedMemorySize, DYN_SMEM);
        attr_set = 1;
    }

    init_kernel<<<8192, 256>>>();
    xcvt_kernel<<<(M_TOK * DD + 255) / 256, 256>>>(x);
    pack_kernel<<<(NLAYERS * KDIM * VDIM + 255) / 256, 256>>>(Ws, bs, Wi, bi, Wt, bt);

    dim3 grid(M_TOK / MT, VDIM / NT);   // 64 x 2 = 128 CTAs, clusters of (2,2)
    for (int t = 0; t < TMAX; t++) {
        for (int l = 0; l < NLAYERS; l++)
            layer_kernel<<<grid, 256, DYN_SMEM>>>(l, t & 1, t);
    }
    output_kernel<<<(out_size + 255) / 256, 256>>>((float*)d_out, out_size);
}

// round 17
// speedup vs baseline: 2.2879x; 1.3030x over previous
#include <cuda_runtime.h>
#include <cuda_bf16.h>
#include <math.h>
#include <stdint.h>

#define M_TOK   8192     // B*S
#define DD      256      // hidden dim
#define KDIM    512      // combined input dim
#define VDIM    512      // virtual output dim (tau/forcing interleaved)
#define NLAYERS 4
#define TMAX    50

#define MT 128           // M tile per CTA
#define NT 256           // N tile per CTA (TMEM D cols)
#define STAGE_BYTES 98304    // Ahi 16K + Alo 16K + Bhi 32K + Blo 32K
#define DYN_SMEM (2*STAGE_BYTES + 1024)   // +1024 for manual alignment

// idesc kind::f16: dtype=F32, atype=btype=BF16, N=256, M=128
#define IDESC 0x8400490u

// Arch gate: tcgen05 only in the sm_103a pass; baseline compute_103 pass
// gets the fp32 FFMA fallback.
#if defined(__CUDA_ARCH__) && (__CUDA_ARCH__ == 1030) && \
    (defined(__CUDA_ARCH_FEAT_SM103_ALL) || defined(__CUDA_ARCH_SPECIFIC__))
#define TC_PATH 1
#else
#define TC_PATH 0
#endif

// ---------------- device globals (allocation-free scratch) ----------------
__device__ __align__(256) float          g_s32[2][NLAYERS][M_TOK*DD];  // fp32 states
__device__ __align__(256) __nv_bfloat16  g_sbh[2][NLAYERS][M_TOK*DD];  // bf16 hi plane (swizzled)
__device__ __align__(256) __nv_bfloat16  g_sbl[2][NLAYERS][M_TOK*DD];  // bf16 lo plane (swizzled)
__device__ __align__(256) float          g_x32[M_TOK*DD];
__device__ __align__(256) __nv_bfloat16  g_xh[M_TOK*DD];               // swizzled
__device__ __align__(256) __nv_bfloat16  g_xl[M_TOK*DD];               // swizzled
__device__ __align__(256) __nv_bfloat16  g_wh[NLAYERS*VDIM*KDIM];      // [l][vt][kb] swizzled blocks
__device__ __align__(256) __nv_bfloat16  g_wl[NLAYERS*VDIM*KDIM];
__device__ __align__(256) float          g_Wp[NLAYERS*KDIM*VDIM];      // fp32 [l][k][v] (fallback)
__device__ float    g_bp[NLAYERS*VDIM];
__device__ int      g_done;
__device__ int      g_result;
__device__ unsigned g_delta;
__device__ int      g_last;
__device__ unsigned g_count;
__device__ unsigned g_gen;      // step generation; bit31 = done

// ---------------- inline PTX helpers ----------------
__device__ __forceinline__ uint32_t smem_u32(const void* p) {
    uint32_t a;
    asm("{ .reg .u64 t; cvta.to.shared.u64 t, %1; cvt.u32.u64 %0, t; }" : "=r"(a) : "l"(p));
    return a;
}

__device__ __forceinline__ uint64_t make_desc(uint32_t addr) {
    const uint64_t base = (2ULL << 61) | (1ULL << 46) | (64ULL << 32) | (1ULL << 16); // SW128, LBO=1, SBO=64
    return base | (uint64_t)((addr >> 4) & 0x3FFF);
}

#define MBAR_INIT(a, c) asm volatile("mbarrier.init.shared.b64 [%0], %1;" :: "r"(a), "r"(c) : "memory")
#define MBAR_EXPECT_TX(a, b) asm volatile("mbarrier.arrive.expect_tx.shared.b64 _, [%0], %1;" :: "r"(a), "r"(b) : "memory")
#define MBAR_WAIT(a, par) do { \
    uint32_t _m = (a), _p = (par), _d; \
    asm volatile("{\n\t.reg .pred p;\n\tmbarrier.try_wait.parity.acquire.cta.shared::cta.b64 p, [%1], %2;\n\tselp.b32 %0, 1, 0, p;\n\t}" \
        : "=r"(_d) : "r"(_m), "r"(_p) : "memory"); \
    if (!_d) { \
        asm volatile("{\n\t.reg .pred P1;\n\tWL_%=:\n\tmbarrier.try_wait.parity.acquire.cta.shared::cta.b64 P1, [%0], %1, 0x989680;\n\t@P1 bra.uni WD_%=;\n\tbra.uni WL_%=;\n\tWD_%=:\n\t}" \
            :: "r"(_m), "r"(_p) : "memory"); \
    } } while (0)

#define CLUSTER_SYNC() do { \
    asm volatile("barrier.cluster.arrive.aligned;" ::: "memory"); \
    asm volatile("barrier.cluster.wait.aligned;" ::: "memory"); } while (0)

#if TC_PATH
#define CP_BULK_MC(dst, src, bytes, mbar, mask) \
    asm volatile("cp.async.bulk.shared::cluster.global.mbarrier::complete_tx::bytes.multicast::cluster [%0], [%1], %2, [%3], %4;" \
        :: "r"(dst), "l"(src), "r"(bytes), "r"(mbar), "h"((uint16_t)(mask)) : "memory")

#define MBAR_ARRIVE_RANK(addr, rank) \
    asm volatile("{\n\t.reg .b32 ra;\n\tmapa.shared::cluster.u32 ra, %0, %1;\n\tmbarrier.arrive.shared::cluster.b64 _, [ra];\n\t}" \
        :: "r"(addr), "r"(rank) : "memory")

#define TM_ALLOC(sa, n)   asm volatile("tcgen05.alloc.cta_group::1.sync.aligned.shared::cta.b32 [%0], %1;" :: "r"(sa), "r"(n) : "memory")
#define TM_DEALLOC(t, n)  asm volatile("tcgen05.dealloc.cta_group::1.sync.aligned.b32 %0, %1;" :: "r"(t), "r"(n))
#define TM_RELINQ()       asm volatile("tcgen05.relinquish_alloc_permit.cta_group::1.sync.aligned;")
#define TM_COMMIT(mb)     asm volatile("tcgen05.commit.cta_group::1.mbarrier::arrive::one.shared::cluster.b64 [%0];" :: "r"(mb) : "memory")
#define TM_WAIT_LD()      asm volatile("tcgen05.wait::ld.sync.aligned;" ::: "memory")
#define TM_FENCE_AFTER()  asm volatile("tcgen05.fence::after_thread_sync;" ::: "memory")
#define TM_FENCE_BEFORE() asm volatile("tcgen05.fence::before_thread_sync;" ::: "memory")

__device__ __forceinline__ void mma_f16_ss(uint32_t d, uint64_t a, uint64_t b, uint32_t idesc, bool en) {
    uint32_t e = en ? 1u : 0u;
    asm volatile(
        "{\n\t.reg .pred p;\n\tsetp.ne.u32 p, %5, 0;\n\t"
        "tcgen05.mma.cta_group::1.kind::f16 [%0], %1, %2, %3, {%4, %4, %4, %4}, p;\n\t}"
        :: "r"(d), "l"(a), "l"(b), "r"(idesc), "r"(0u), "r"(e) : "memory");
}

#define TM_LD_X32(r, ta) \
    asm volatile("tcgen05.ld.sync.aligned.32x32b.x32.b32 " \
        "{%0,%1,%2,%3,%4,%5,%6,%7,%8,%9,%10,%11,%12,%13,%14,%15," \
        "%16,%17,%18,%19,%20,%21,%22,%23,%24,%25,%26,%27,%28,%29,%30,%31}, [%32];" \
        : "=r"((r)[0]),"=r"((r)[1]),"=r"((r)[2]),"=r"((r)[3]),"=r"((r)[4]),"=r"((r)[5]),"=r"((r)[6]),"=r"((r)[7]), \
          "=r"((r)[8]),"=r"((r)[9]),"=r"((r)[10]),"=r"((r)[11]),"=r"((r)[12]),"=r"((r)[13]),"=r"((r)[14]),"=r"((r)[15]), \
          "=r"((r)[16]),"=r"((r)[17]),"=r"((r)[18]),"=r"((r)[19]),"=r"((r)[20]),"=r"((r)[21]),"=r"((r)[22]),"=r"((r)[23]), \
          "=r"((r)[24]),"=r"((r)[25]),"=r"((r)[26]),"=r"((r)[27]),"=r"((r)[28]),"=r"((r)[29]),"=r"((r)[30]),"=r"((r)[31]) \
        : "r"(ta))
#endif // TC_PATH

// ---------------------------------------------------------------
__global__ void init_kernel() {
    size_t idx = (size_t)blockIdx.x * blockDim.x + threadIdx.x;
    float4 z = make_float4(0.f, 0.f, 0.f, 0.f);
    if (idx < (size_t)NLAYERS * M_TOK * DD / 4) ((float4*)&g_s32[0][0][0])[idx] = z;
    if (idx < (size_t)NLAYERS * M_TOK * DD / 8) {
        ((float4*)&g_sbh[0][0][0])[idx] = z;
        ((float4*)&g_sbl[0][0][0])[idx] = z;
    }
    if (idx == 0) {
        g_done = 0; g_result = TMAX; g_delta = 0u; g_last = 0; g_count = 0u; g_gen = 0u;
    }
}

__global__ void xcvt_kernel(const float* __restrict__ x) {
    int idx = blockIdx.x * blockDim.x + threadIdx.x;
    if (idx < M_TOK * DD) {
        float v = x[idx];
        g_x32[idx] = v;
        int m = idx >> 8, d = idx & 255;
        int kb = d >> 6, c = d & 63;
        size_t o = ((size_t)kb * 8192 + m) * 64 + (c ^ ((m & 7) << 3));  // swizzled
        __nv_bfloat16 hi = __float2bfloat16(v);
        g_xh[o] = hi;
        g_xl[o] = __float2bfloat16(v - __bfloat162float(hi));
    }
}

__global__ void pack_kernel(const float* __restrict__ Ws, const float* __restrict__ bs,
                            const float* __restrict__ Wi, const float* __restrict__ bi,
                            const float* __restrict__ Wt, const float* __restrict__ bt) {
    int idx = blockIdx.x * blockDim.x + threadIdx.x;
    int total = NLAYERS * KDIM * VDIM;
    if (idx < total) {
        int l = idx / (KDIM * VDIM);
        int rem = idx % (KDIM * VDIM);
        int k = rem / VDIM;
        int v = rem % VDIM;
        int d = v >> 1, half = v & 1;
        float w;
        if (half == 0)      w = Wt[(l * DD + d) * KDIM + k];
        else if (k < DD)    w = Wi[(l * DD + d) * DD + k];
        else                w = Ws[(l * DD + d) * DD + (k - DD)];
        g_Wp[idx] = w;                                    // fp32 [l][k][v] (fallback)
        int vt = v >> 8, vl = v & 255, kb = k >> 6, c = k & 63;
        size_t o = (size_t)(((l * 2 + vt) * 8 + kb)) * 16384 + vl * 64 + (c ^ ((vl & 7) << 3));
        __nv_bfloat16 hi = __float2bfloat16(w);
        g_wh[o] = hi;
        g_wl[o] = __float2bfloat16(w - __bfloat162float(hi));
    }
    if (idx < NLAYERS * VDIM) {
        int l = idx / VDIM, v = idx % VDIM, d = v >> 1, half = v & 1;
        g_bp[idx] = half ? (bs[l * DD + d] + bi[l * DD + d]) : bt[l * DD + d];
    }
}

// epilogue scalar: intrinsic transcendentals (inf-safe at saturation)
__device__ __forceinline__ float epi_update(float pt, float pf, float h, float& dmax) {
    float e   = __expf(-pt);
    float tau = __fdividef(1.f, 1.f + e);
    float ax  = fabsf(pf);
    float e2  = __expf(ax + ax);
    float th  = 1.f - __fdividef(2.f, e2 + 1.f);
    float forc = copysignf(th, pf);
    float hn = h + 0.05f * (forc - __fdividef(h, tau + 1e-6f));
    hn = fminf(10.f, fmaxf(-10.f, hn));
    dmax = fmaxf(dmax, fabsf(hn - h));
    return hn;
}

// grid-wide step barrier; returns 1 if converged (done) after step t.
__device__ __forceinline__ int step_barrier(int t) {
    unsigned old = atomicAdd(&g_count, 1u);
    if (old == 127u) {                       // last CTA of this step
        unsigned dbits = atomicMax(&g_delta, 0u);
        g_count = 0u;
        g_last = (t & 1) ^ 1;
        unsigned donebit = 0u;
        if (__uint_as_float(dbits) < 1e-3f) { g_done = 1; g_result = t; donebit = 0x80000000u; }
        g_delta = 0u;
        __threadfence();
        atomicExch(&g_gen, (unsigned)(t + 1) | donebit);
    }
    unsigned gv;
    do { __nanosleep(64); gv = atomicAdd(&g_gen, 0u); } while ((gv & 0x7fffffffu) < (unsigned)(t + 1));
    return (int)(gv >> 31);
}

// ---------------- persistent kernel: full fixed-point iteration ----------------
__global__ void __launch_bounds__(256, 1) __cluster_dims__(2, 2, 1)
persist_kernel() {
    extern __shared__ char dynsmem[];
    const int tid = threadIdx.x;

#if TC_PATH
    __shared__ uint32_t s_tmem;
    __shared__ __align__(8) uint64_t s_mbar[6];   // full[2], mma[2], empty[2]
    __shared__ float s_red[8];
    __shared__ int s_done;

    const int wid = tid >> 5, lane = tid & 31;
    const int m0 = blockIdx.x * MT;
    const int vt = blockIdx.y;
    const int v0 = vt * NT;
    const int cx = blockIdx.x & 1;
    const int cy = blockIdx.y & 1;
    const uint16_t amask = (uint16_t)((1u << cx) | (1u << (cx + 2)));
    const uint16_t bmask = (uint16_t)(3u << (2 * cy));

    uint32_t full_mb[2], mma_mb[2], empty_mb[2];
    full_mb[0]  = smem_u32(&s_mbar[0]); full_mb[1]  = smem_u32(&s_mbar[1]);
    mma_mb[0]   = smem_u32(&s_mbar[2]); mma_mb[1]   = smem_u32(&s_mbar[3]);
    empty_mb[0] = smem_u32(&s_mbar[4]); empty_mb[1] = smem_u32(&s_mbar[5]);
    if (tid == 0) {
        MBAR_INIT(full_mb[0], 1); MBAR_INIT(full_mb[1], 1);
        MBAR_INIT(mma_mb[0], 1);  MBAR_INIT(mma_mb[1], 1);
        MBAR_INIT(empty_mb[0], 4); MBAR_INIT(empty_mb[1], 4);
    }
    if (wid == 0) TM_ALLOC(smem_u32(&s_tmem), NT);
    __syncthreads();
    uint32_t tmem;
    asm volatile("ld.shared.b32 %0, [%1];" : "=r"(tmem) : "r"(smem_u32(&s_tmem)));

    const uint32_t sbase = (smem_u32(dynsmem) + 1023u) & ~1023u;

    CLUSTER_SYNC();   // all peers' mbarriers ready before any multicast

    // persistent mbarrier parity bits (tid0 only): f0 f1 m0 m1 e0 e1
    unsigned par = 0u;
#define PAR_GET(b)  ((par >> (b)) & 1u)
#define PAR_TGL(b)  (par ^= (1u << (b)))

    for (int t = 0; t < TMAX; t++) {
        const int rb = t & 1;
        for (int l = 0; l < NLAYERS; l++) {
            const __nv_bfloat16* __restrict__ cin_h = (l == 0) ? g_xh : g_sbh[rb ^ 1][l - 1];
            const __nv_bfloat16* __restrict__ cin_l = (l == 0) ? g_xl : g_sbl[rb ^ 1][l - 1];
            const __nv_bfloat16* __restrict__ hp_h  = g_sbh[rb][l];
            const __nv_bfloat16* __restrict__ hp_l  = g_sbl[rb][l];
            const float* __restrict__ hp32          = g_s32[rb][l];
            float* __restrict__ o32                 = g_s32[rb ^ 1][l];
            __nv_bfloat16* __restrict__ obh         = g_sbh[rb ^ 1][l];
            __nv_bfloat16* __restrict__ obl         = g_sbl[rb ^ 1][l];
            const __nv_bfloat16* __restrict__ wbh   = g_wh + (size_t)((l * 2 + vt) * 8) * 16384;
            const __nv_bfloat16* __restrict__ wbl   = g_wl + (size_t)((l * 2 + vt) * 8) * 16384;

            if (tid == 0) {
                auto issue_loads = [&](int kb, uint32_t stage, uint32_t fmb) {
                    MBAR_EXPECT_TX(fmb, (uint32_t)STAGE_BYTES);
                    const __nv_bfloat16* ah; const __nv_bfloat16* al; int akb;
                    if (kb < 4) { ah = cin_h; al = cin_l; akb = kb; }
                    else        { ah = hp_h;  al = hp_l;  akb = kb - 4; }
                    const __nv_bfloat16* asrc = (cy ? al : ah) + ((size_t)akb * 8192 + m0) * 64;
                    CP_BULK_MC(stage + cy * 16384, asrc, 16384u, fmb, amask);
                    const __nv_bfloat16* bsrc = (cx ? wbl : wbh) + (size_t)kb * 16384;
                    CP_BULK_MC(stage + 32768 + cx * 32768, bsrc, 32768u, fmb, bmask);
                };

                // stage buffers are free here: own final mma waits + cluster sync
                // at the end of the previous layer cover all 4 CTAs' reads.
                issue_loads(0, sbase, full_mb[0]);
                issue_loads(1, sbase + STAGE_BYTES, full_mb[1]);

                for (int kb = 0; kb < 8; kb++) {
                    const int s = kb & 1;
                    const uint32_t stage = sbase + s * STAGE_BYTES;
                    MBAR_WAIT(full_mb[s], PAR_GET(0 + s)); PAR_TGL(0 + s);

                    uint64_t dah = make_desc(stage);
                    uint64_t dal = make_desc(stage + 16384);
                    uint64_t dbh = make_desc(stage + 32768);
                    uint64_t dbl = make_desc(stage + 65536);
#pragma unroll
                    for (int pass = 0; pass < 3; pass++) {
                        uint64_t da = (pass == 2) ? dal : dah;
                        uint64_t db = (pass == 1) ? dbl : dbh;
#pragma unroll
                        for (int kc = 0; kc < 4; kc++)
                            mma_f16_ss(tmem, da + kc * 2, db + kc * 2, IDESC,
                                       !(kb == 0 && pass == 0 && kc == 0));
                    }
                    TM_COMMIT(mma_mb[s]);

                    // R8-proven recycle: wait CURRENT stage's MMAs, then
                    // refill the same stage for kb+2 (two-stage prefetch lead).
                    if (kb < 6) {
                        MBAR_WAIT(mma_mb[s], PAR_GET(2 + s)); PAR_TGL(2 + s);
#pragma unroll
                        for (int r = 0; r < 4; r++) MBAR_ARRIVE_RANK(empty_mb[s], r);
                        MBAR_WAIT(empty_mb[s], PAR_GET(4 + s)); PAR_TGL(4 + s);
                        issue_loads(kb + 2, stage, full_mb[s]);
                    }
                }
                // consume the two outstanding commits (kb=6 -> mma0, kb=7 -> mma1)
                MBAR_WAIT(mma_mb[0], PAR_GET(2)); PAR_TGL(2);
                MBAR_WAIT(mma_mb[1], PAR_GET(3)); PAR_TGL(3);
            }
            __syncthreads();
            TM_FENCE_AFTER();

            // ---- fused epilogue: 8 warps; warp w -> rows (w&3)*32, col-half w>>2 ----
            float dmax = 0.f;
            {
                const int m = m0 + (wid & 3) * 32 + lane;
                const int cb0 = (wid >> 2) * 4;
                const float* hp = hp32 + (size_t)m * DD;
                float* orow = o32 + (size_t)m * DD;
                const int sw = (m & 7) << 3;
#pragma unroll
                for (int ci = 0; ci < 4; ci++) {
                    const int cb = cb0 + ci;
                    uint32_t r[32];
                    TM_LD_X32(r, tmem + cb * 32);
                    TM_WAIT_LD();
                    const int dbase = (v0 >> 1) + cb * 16;
                    const float* bp = &g_bp[l * VDIM + v0 + cb * 32];
                    __align__(16) float hnv[16];
                    __align__(16) __nv_bfloat16 hib[16], lob[16];
#pragma unroll
                    for (int j = 0; j < 16; j++) {
                        float pt = __uint_as_float(r[2 * j])     + bp[2 * j];
                        float pf = __uint_as_float(r[2 * j + 1]) + bp[2 * j + 1];
                        float hn = epi_update(pt, pf, hp[dbase + j], dmax);
                        hnv[j] = hn;
                        __nv_bfloat16 hi = __float2bfloat16(hn);
                        hib[j] = hi;
                        lob[j] = __float2bfloat16(hn - __bfloat162float(hi));
                    }
#pragma unroll
                    for (int q = 0; q < 4; q++)
                        *(float4*)&orow[dbase + q * 4] = *(float4*)&hnv[q * 4];
                    const int kbd = dbase >> 6, c0 = dbase & 63;
                    const size_t eb = ((size_t)kbd * 8192 + m) * 64;
                    *(uint4*)&obh[eb + (c0 ^ sw)]       = *(uint4*)&hib[0];
                    *(uint4*)&obh[eb + ((c0 + 8) ^ sw)] = *(uint4*)&hib[8];
                    *(uint4*)&obl[eb + (c0 ^ sw)]       = *(uint4*)&lob[0];
                    *(uint4*)&obl[eb + ((c0 + 8) ^ sw)] = *(uint4*)&lob[8];
                }
                TM_FENCE_BEFORE();
#pragma unroll
                for (int o = 16; o; o >>= 1) dmax = fmaxf(dmax, __shfl_xor_sync(0xffffffffu, dmax, o));
                if (lane == 0) s_red[wid] = dmax;
            }
            __threadfence();   // publish epilogue stores to peer CTAs' TMA reads
            __syncthreads();
            if (tid == 0) {
                float v = s_red[0];
#pragma unroll
                for (int w = 1; w < 8; w++) v = fmaxf(v, s_red[w]);
                atomicMax(&g_delta, __float_as_uint(v));
            }
            CLUSTER_SYNC();    // layer l outputs visible to layer l+1 loads
        }

        if (tid == 0) s_done = step_barrier(t);
        __syncthreads();
        if (s_done) break;
    }

    __syncthreads();
    if (wid == 0) { TM_RELINQ(); TM_DEALLOC(tmem, NT); }

#else
    // ================= fp32 FFMA persistent fallback (baseline compile pass) =================
    float* As = (float*)dynsmem;                  // [16][128]
    float* Bs = (float*)(dynsmem + 16 * 128 * 4); // [16][64]
    __shared__ float red[8];
    __shared__ int s_done2;

    const int ty = tid >> 4, tx = tid & 15;
    const int m0 = blockIdx.x * 128;

    for (int t = 0; t < TMAX; t++) {
        const int rb = t & 1;
        for (int l = 0; l < NLAYERS; l++) {
            const float* __restrict__ curin = (l == 0) ? g_x32 : g_s32[rb ^ 1][l - 1];
            const float* __restrict__ hprev = g_s32[rb][l];
            float* __restrict__ hout        = g_s32[rb ^ 1][l];
            const float* __restrict__ Wp    = &g_Wp[l * KDIM * VDIM];

            float dmax_all = 0.f;
            for (int vc = 0; vc < 4; vc++) {
                int v0 = blockIdx.y * NT + vc * 64;
                float acc[8][4];
#pragma unroll
                for (int i = 0; i < 8; i++)
#pragma unroll
                    for (int j = 0; j < 4; j++) acc[i][j] = 0.f;

                for (int k0 = 0; k0 < KDIM; k0 += 16) {
                    const float* Asrc = (k0 < DD) ? curin : hprev;
                    int kb2 = k0 & (DD - 1);
                    __syncthreads();
#pragma unroll
                    for (int s = 0; s < 2; s++) {
                        int slot = tid * 2 + s;
                        int ml = slot >> 2, k4 = slot & 3;
                        float4 va = *(const float4*)&Asrc[(size_t)(m0 + ml) * DD + kb2 + k4 * 4];
                        As[(k4 * 4 + 0) * 128 + ml] = va.x; As[(k4 * 4 + 1) * 128 + ml] = va.y;
                        As[(k4 * 4 + 2) * 128 + ml] = va.z; As[(k4 * 4 + 3) * 128 + ml] = va.w;
                    }
                    {
                        int kk = tid >> 4, v4 = tid & 15;
                        *(float4*)&Bs[kk * 64 + v4 * 4] =
                            *(const float4*)&Wp[(size_t)(k0 + kk) * VDIM + v0 + v4 * 4];
                    }
                    __syncthreads();
#pragma unroll
                    for (int kk = 0; kk < 16; kk++) {
                        float4 a0 = *(const float4*)&As[kk * 128 + ty * 8];
                        float4 a1 = *(const float4*)&As[kk * 128 + ty * 8 + 4];
                        float4 bb = *(const float4*)&Bs[kk * 64 + tx * 4];
                        float a[8] = {a0.x, a0.y, a0.z, a0.w, a1.x, a1.y, a1.z, a1.w};
                        float b[4] = {bb.x, bb.y, bb.z, bb.w};
#pragma unroll
                        for (int i = 0; i < 8; i++)
#pragma unroll
                            for (int j = 0; j < 4; j++) acc[i][j] += a[i] * b[j];
                    }
                }

                float bT0 = g_bp[l * VDIM + v0 + tx * 4 + 0];
                float bF0 = g_bp[l * VDIM + v0 + tx * 4 + 1];
                float bT1 = g_bp[l * VDIM + v0 + tx * 4 + 2];
                float bF1 = g_bp[l * VDIM + v0 + tx * 4 + 3];
                int d0 = (v0 >> 1) + tx * 2;
#pragma unroll
                for (int i = 0; i < 8; i++) {
                    int m = m0 + ty * 8 + i;
#pragma unroll
                    for (int q = 0; q < 2; q++) {
                        float hn = epi_update(acc[i][2 * q] + (q ? bT1 : bT0),
                                              acc[i][2 * q + 1] + (q ? bF1 : bF0),
                                              hprev[(size_t)m * DD + d0 + q], dmax_all);
                        hout[(size_t)m * DD + d0 + q] = hn;
                    }
                }
            }
#pragma unroll
            for (int o = 16; o; o >>= 1) dmax_all = fmaxf(dmax_all, __shfl_xor_sync(0xffffffffu, dmax_all, o));
            if ((tid & 31) == 0) red[tid >> 5] = dmax_all;
            __threadfence();
            __syncthreads();
            if (tid == 0) {
                float v = red[0];
#pragma unroll
                for (int w = 1; w < 8; w++) v = fmaxf(v, red[w]);
                atomicMax(&g_delta, __float_as_uint(v));
            }
            CLUSTER_SYNC();
        }
        if (tid == 0) s_done2 = step_barrier(t);
        __syncthreads();
        if (s_done2) break;
    }
#endif
}

__global__ void output_kernel(float* __restrict__ out, int n) {
    int idx = blockIdx.x * blockDim.x + threadIdx.x;
    if (idx >= n) return;
    if (idx < M_TOK * DD) out[idx] = g_s32[g_last][NLAYERS - 1][idx];
    else                  out[idx] = (float)g_result;
}

// ---------------------------------------------------------------
extern "C" void kernel_launch(void* const* d_in, const int* in_sizes, int n_in,
                              void* d_out, int out_size) {
    const float* x  = (const float*)d_in[0];
    const float* Ws = (const float*)d_in[1];
    const float* bs = (const float*)d_in[2];
    const float* Wi = (const float*)d_in[3];
    const float* bi = (const float*)d_in[4];
    const float* Wt = (const float*)d_in[5];
    const float* bt = (const float*)d_in[6];

    static int attr_set = 0;
    if (!attr_set) {
        cudaFuncSetAttribute(persist_kernel, cudaFuncAttributeMaxDynamicSharedMemorySize, DYN_SMEM);
        attr_set = 1;
    }

    init_kernel<<<8192, 256>>>();
    xcvt_kernel<<<(M_TOK * DD + 255) / 256, 256>>>(x);
    pack_kernel<<<(NLAYERS * KDIM * VDIM + 255) / 256, 256>>>(Ws, bs, Wi, bi, Wt, bt);

    dim3 grid(M_TOK / MT, VDIM / NT);   // 64 x 2 = 128 CTAs, one resident wave
    persist_kernel<<<grid, 256, DYN_SMEM>>>();

    output_kernel<<<(out_size + 255) / 256, 256>>>((float*)d_out, out_size);
}